// round 5
// baseline (speedup 1.0000x reference)
#include <cuda_runtime.h>
#include <cuda_bf16.h>
#include <cstdint>

// VectorQuantizer via mma.sync.m16n8k16 bf16 (HMMA on sm_103):
// 3-term bf16-split GEMM distances, FMNMX-filtered top-2 argmin, exact fp32
// re-rank. Round 5: smem overlap (3 CTAs/SM), c-grouped layout (LDS.128
// fragments), filtered epilogue, parallel prep.

#define DIMS    64
#define KCODES  1024
#define HW      1024
#define THREADS 128
#define NPOS    65536
#define NBLOCKS 512
#define PITCH   272                       // [hi 128B | lo 128B | pad 16B], 17x16B
#define TILE_CODES 128
#define TILE_BYTES (TILE_CODES * PITCH)   // 34816

// smem layout (dynamic): B1 overlaps the A staging region.
#define SM_B0    0                        // 34816
#define SM_AB1   34816                    // A rows, then B tile (odd) : 34816
#define SM_CN    69632                    // 1024 f32
#define SM_I1    73728                    // 128 int
#define SM_I2    74240                    // 128 int
#define SM_RED   74752                    // 128 f32
#define SM_TOTAL 75264

__device__ float g_cnorm[KCODES];
__device__ float g_partial[NBLOCKS];
__device__ __align__(16) unsigned char g_cb[KCODES * PITCH];

// Row layout (both A and B, per 272B row): hi block [0,128), lo block [128,256).
// Within a block, lane-c group c owns bytes [c*32, c*32+32): word w (4B) holds
// bf16 dims (8w+2c, 8w+2c+1). Fragment slice for k-step kt: words 2kt (k=16kt+2c)
// and 2kt+1 (k=16kt+2c+8) -> one uint4 covers kt=0,1; next uint4 kt=2,3.

// ---------------- helpers ----------------
__device__ __forceinline__ uint32_t smem_u32(const void* p) {
    uint32_t a;
    asm("{ .reg .u64 t; cvta.to.shared.u64 t, %1; cvt.u32.u64 %0, t; }"
        : "=r"(a) : "l"(p));
    return a;
}

__device__ __forceinline__ uint32_t pack_bf16(float v0, float v1) {
    return (uint32_t)__bfloat16_as_ushort(__float2bfloat16(v0)) |
           ((uint32_t)__bfloat16_as_ushort(__float2bfloat16(v1)) << 16);
}

#define MMA(d, a, bb) \
    asm volatile("mma.sync.aligned.m16n8k16.row.col.f32.bf16.bf16.f32 " \
                 "{%0,%1,%2,%3}, {%4,%5,%6,%7}, {%8,%9}, {%0,%1,%2,%3};" \
                 : "+f"((d)[0]), "+f"((d)[1]), "+f"((d)[2]), "+f"((d)[3]) \
                 : "r"((a)[0]), "r"((a)[1]), "r"((a)[2]), "r"((a)[3]), \
                   "r"((bb)[0]), "r"((bb)[1]))

__device__ __forceinline__ void cpa16(uint32_t dst, const void* src) {
    asm volatile("cp.async.cg.shared.global [%0], [%1], 16;" :: "r"(dst), "l"(src));
}
#define CPA_COMMIT() asm volatile("cp.async.commit_group;" ::: "memory")
#define CPA_WAIT1()  asm volatile("cp.async.wait_group 1;" ::: "memory")

#define UPD(ri, s, ci) \
    do { if ((s) < best[ri]) { best2[ri] = best[ri]; i2[ri] = bidx[ri]; \
                               best[ri] = (s); bidx[ri] = (ci); } \
         else if ((s) < best2[ri]) { best2[ri] = (s); i2[ri] = (ci); } } while (0)

// ---------------------------------------------------------------------------
// Prep: 8 threads/code. Thread j of a code handles dims 8j..8j+7 (word w=j of
// every c-group), converts to hi/lo bf16, and octet-reduces ||c||^2.
// ---------------------------------------------------------------------------
__global__ void prep_kernel(const float* __restrict__ cb) {
    const int idx = blockIdx.x * blockDim.x + threadIdx.x;   // 8192 threads
    const int k = idx >> 3;
    const int j = idx & 7;
    const float2* row = (const float2*)(cb + k * DIMS + j * 8);
    unsigned char* dst = g_cb + (size_t)k * PITCH;
    float cn = 0.f;
    #pragma unroll
    for (int c = 0; c < 4; ++c) {
        float2 v = row[c];                      // dims (8j+2c, 8j+2c+1)
        cn = fmaf(v.y, v.y, fmaf(v.x, v.x, cn));
        __nv_bfloat16 h0 = __float2bfloat16(v.x), h1 = __float2bfloat16(v.y);
        *(uint32_t*)(dst + c * 32 + j * 4) =
            (uint32_t)__bfloat16_as_ushort(h0) |
            ((uint32_t)__bfloat16_as_ushort(h1) << 16);
        *(uint32_t*)(dst + 128 + c * 32 + j * 4) =
            pack_bf16(v.x - __bfloat162float(h0), v.y - __bfloat162float(h1));
    }
    cn += __shfl_down_sync(0xffffffffu, cn, 4);
    cn += __shfl_down_sync(0xffffffffu, cn, 2);
    cn += __shfl_down_sync(0xffffffffu, cn, 1);
    if (j == 0) g_cnorm[k] = cn;
}

// ---------------------------------------------------------------------------
// Main kernel
// ---------------------------------------------------------------------------
__global__ __launch_bounds__(THREADS, 3) void vq_mma_kernel(
    const float* __restrict__ latents,
    const float* __restrict__ cb,
    float* __restrict__ out)
{
    extern __shared__ unsigned char smem[];
    const uint32_t sb = smem_u32(smem);
    const int tid  = threadIdx.x;
    const int w    = tid >> 5;
    const int lane = tid & 31;
    const int g    = lane >> 2;
    const int c    = lane & 3;

    // prefetch B tile 0 into B0 region
    #pragma unroll
    for (int i = 0; i < 17; ++i)
        cpa16(sb + SM_B0 + tid * 16 + i * 2048, g_cb + tid * 16 + i * 2048);
    CPA_COMMIT();

    // cnorm -> smem (float4 strided)
    #pragma unroll
    for (int i = tid; i < KCODES / 4; i += THREADS)
        ((float4*)(smem + SM_CN))[i] = ((const float4*)g_cnorm)[i];

    // ---- build A row in AB1 region (c-grouped hi/lo layout) ----
    const int p  = blockIdx.x * THREADS + tid;
    const int b  = p >> 10;
    const int hw = p & (HW - 1);
    const float* xin = latents + (size_t)b * (DIMS * HW) + hw;
    unsigned char* arow = smem + SM_AB1 + tid * PITCH;
    float xn0 = 0.f, xn1 = 0.f;
    #pragma unroll
    for (int cc = 0; cc < 4; ++cc)
        #pragma unroll
        for (int ww = 0; ww < 8; ++ww) {
            const int d = 8 * ww + 2 * cc;
            float v0 = xin[d * HW], v1 = xin[(d + 1) * HW];
            xn0 = fmaf(v0, v0, xn0); xn1 = fmaf(v1, v1, xn1);
            __nv_bfloat16 h0 = __float2bfloat16(v0), h1 = __float2bfloat16(v1);
            *(uint32_t*)(arow + cc * 32 + ww * 4) =
                (uint32_t)__bfloat16_as_ushort(h0) |
                ((uint32_t)__bfloat16_as_ushort(h1) << 16);
            *(uint32_t*)(arow + 128 + cc * 32 + ww * 4) =
                pack_bf16(v0 - __bfloat162float(h0), v1 - __bfloat162float(h1));
        }
    const float xnorm = xn0 + xn1;
    __syncthreads();

    // ---- load A fragments (resident): 16x LDS.128 ----
    // uint4 at row base + half + c*32 covers kt0,1; +16 covers kt2,3.
    // word 2kt -> a0/a1 slot (k=16kt+2c), word 2kt+1 -> a2/a3 slot (k=16kt+2c+8)
    uint32_t aH[2][4][4], aL[2][4][4];
    const int rbase = 32 * w + g;
    #pragma unroll
    for (int mt = 0; mt < 2; ++mt) {
        const unsigned char* r0 = smem + SM_AB1 + (rbase + 16 * mt) * PITCH + c * 32;
        const unsigned char* r8 = r0 + 8 * PITCH;
        #pragma unroll
        for (int half = 0; half < 2; ++half) {
            const int hb = half * 128;
            uint4 q0a = *(const uint4*)(r0 + hb);
            uint4 q0b = *(const uint4*)(r0 + hb + 16);
            uint4 q8a = *(const uint4*)(r8 + hb);
            uint4 q8b = *(const uint4*)(r8 + hb + 16);
            uint32_t (*A)[4][4] = half ? aL : aH;
            A[mt][0][0] = q0a.x; A[mt][0][2] = q0a.y;
            A[mt][1][0] = q0a.z; A[mt][1][2] = q0a.w;
            A[mt][2][0] = q0b.x; A[mt][2][2] = q0b.y;
            A[mt][3][0] = q0b.z; A[mt][3][2] = q0b.w;
            A[mt][0][1] = q8a.x; A[mt][0][3] = q8a.y;
            A[mt][1][1] = q8a.z; A[mt][1][3] = q8a.w;
            A[mt][2][1] = q8b.x; A[mt][2][3] = q8b.y;
            A[mt][3][1] = q8b.z; A[mt][3][3] = q8b.w;
        }
    }
    __syncthreads();   // A region free for B tile 1

    // prefetch B tile 1 into AB1 region
    #pragma unroll
    for (int i = 0; i < 17; ++i)
        cpa16(sb + SM_AB1 + tid * 16 + i * 2048,
              g_cb + TILE_BYTES + tid * 16 + i * 2048);
    CPA_COMMIT();

    float best[4]  = {3.4e38f, 3.4e38f, 3.4e38f, 3.4e38f};
    float best2[4] = {3.4e38f, 3.4e38f, 3.4e38f, 3.4e38f};
    int   bidx[4]  = {0, 0, 0, 0};
    int   i2[4]    = {0, 0, 0, 0};

    #pragma unroll 1
    for (int tb = 0; tb < 8; ++tb) {
        CPA_WAIT1();
        __syncthreads();
        const unsigned char* bbuf = smem + ((tb & 1) ? SM_AB1 : SM_B0);

        #pragma unroll 1
        for (int np = 0; np < 8; ++np) {
            // B fragments: 8x LDS.128 per np
            uint32_t bH[2][4][2], bL[2][4][2];
            #pragma unroll
            for (int j = 0; j < 2; ++j) {
                const unsigned char* rb =
                    bbuf + ((2 * np + j) * 8 + g) * PITCH + c * 32;
                uint4 h0 = *(const uint4*)(rb);
                uint4 h1 = *(const uint4*)(rb + 16);
                uint4 l0 = *(const uint4*)(rb + 128);
                uint4 l1 = *(const uint4*)(rb + 144);
                bH[j][0][0] = h0.x; bH[j][0][1] = h0.y;
                bH[j][1][0] = h0.z; bH[j][1][1] = h0.w;
                bH[j][2][0] = h1.x; bH[j][2][1] = h1.y;
                bH[j][3][0] = h1.z; bH[j][3][1] = h1.w;
                bL[j][0][0] = l0.x; bL[j][0][1] = l0.y;
                bL[j][1][0] = l0.z; bL[j][1][1] = l0.w;
                bL[j][2][0] = l1.x; bL[j][2][1] = l1.y;
                bL[j][3][0] = l1.z; bL[j][3][1] = l1.w;
            }
            float D[2][2][4];
            #pragma unroll
            for (int j = 0; j < 2; ++j)
                #pragma unroll
                for (int mt = 0; mt < 2; ++mt)
                    #pragma unroll
                    for (int q = 0; q < 4; ++q) D[j][mt][q] = 0.f;

            #pragma unroll
            for (int kt = 0; kt < 4; ++kt) {
                MMA(D[0][0], aH[0][kt], bH[0][kt]);
                MMA(D[0][1], aH[1][kt], bH[0][kt]);
                MMA(D[1][0], aH[0][kt], bH[1][kt]);
                MMA(D[1][1], aH[1][kt], bH[1][kt]);
                MMA(D[0][0], aL[0][kt], bH[0][kt]);
                MMA(D[0][1], aL[1][kt], bH[0][kt]);
                MMA(D[1][0], aL[0][kt], bH[1][kt]);
                MMA(D[1][1], aL[1][kt], bH[1][kt]);
                MMA(D[0][0], aH[0][kt], bL[0][kt]);
                MMA(D[0][1], aH[1][kt], bL[0][kt]);
                MMA(D[1][0], aH[0][kt], bL[1][kt]);
                MMA(D[1][1], aH[1][kt], bL[1][kt]);
            }

            // ---- filtered top-2 epilogue ----
            const int cb0 = tb * 128 + (2 * np) * 8 + 2 * c;   // j=0 col base
            const int cb1 = cb0 + 8;                           // j=1 col base
            const float2 cnA = *(const float2*)(smem + SM_CN + cb0 * 4);
            const float2 cnB = *(const float2*)(smem + SM_CN + cb1 * 4);
            #pragma unroll
            for (int mt = 0; mt < 2; ++mt) {
                // row rbase+16mt  (D[.][mt][0..1])
                {
                    const int r = 2 * mt;
                    float s0 = fmaf(-2.f, D[0][mt][0], cnA.x);
                    float s1 = fmaf(-2.f, D[0][mt][1], cnA.y);
                    float s2 = fmaf(-2.f, D[1][mt][0], cnB.x);
                    float s3 = fmaf(-2.f, D[1][mt][1], cnB.y);
                    float m = fminf(fminf(s0, s1), fminf(s2, s3));
                    if (m < best2[r]) {
                        UPD(r, s0, cb0); UPD(r, s1, cb0 + 1);
                        UPD(r, s2, cb1); UPD(r, s3, cb1 + 1);
                    }
                }
                // row rbase+16mt+8 (D[.][mt][2..3])
                {
                    const int r = 2 * mt + 1;
                    float s0 = fmaf(-2.f, D[0][mt][2], cnA.x);
                    float s1 = fmaf(-2.f, D[0][mt][3], cnA.y);
                    float s2 = fmaf(-2.f, D[1][mt][2], cnB.x);
                    float s3 = fmaf(-2.f, D[1][mt][3], cnB.y);
                    float m = fminf(fminf(s0, s1), fminf(s2, s3));
                    if (m < best2[r]) {
                        UPD(r, s0, cb0); UPD(r, s1, cb0 + 1);
                        UPD(r, s2, cb1); UPD(r, s3, cb1 + 1);
                    }
                }
            }
        }

        __syncthreads();   // all readers done with buf[tb&1]
        if (tb + 2 < 8) {
            const uint32_t bdst = sb + ((tb & 1) ? SM_AB1 : SM_B0);
            #pragma unroll
            for (int i = 0; i < 17; ++i)
                cpa16(bdst + tid * 16 + i * 2048,
                      g_cb + (size_t)(tb + 2) * TILE_BYTES + tid * 16 + i * 2048);
        }
        CPA_COMMIT();      // empty group when no prefetch -> uniform accounting
    }

    // ---- merge top-2 across the 4 lanes (c) sharing each row ----
    #pragma unroll
    for (int m = 1; m <= 2; m <<= 1) {
        #pragma unroll
        for (int r = 0; r < 4; ++r) {
            float ob  = __shfl_xor_sync(0xffffffffu, best[r], m);
            int   oi  = __shfl_xor_sync(0xffffffffu, bidx[r], m);
            float ob2 = __shfl_xor_sync(0xffffffffu, best2[r], m);
            int   oi2 = __shfl_xor_sync(0xffffffffu, i2[r], m);
            bool ow = (ob < best[r]) || (ob == best[r] && oi < bidx[r]);
            float nb  = ow ? ob : best[r];  int nbi = ow ? oi : bidx[r];
            float c1  = ow ? best[r] : ob;  int c1i = ow ? bidx[r] : oi;
            float c2  = ow ? ob2 : best2[r]; int c2i = ow ? oi2 : i2[r];
            bool s2 = (c2 < c1) || (c2 == c1 && c2i < c1i);
            best[r] = nb; bidx[r] = nbi;
            best2[r] = s2 ? c2 : c1; i2[r] = s2 ? c2i : c1i;
        }
    }
    int* sI1 = (int*)(smem + SM_I1);
    int* sI2 = (int*)(smem + SM_I2);
    if (c == 0) {
        #pragma unroll
        for (int r = 0; r < 4; ++r) {
            sI1[rbase + 8 * r] = bidx[r];
            sI2[rbase + 8 * r] = i2[r];
        }
    }
    __syncthreads();

    // ---- exact fp32 re-rank of the 2 candidates ----
    const int cA = sI1[tid], cB = sI2[tid];
    const float4* pa = (const float4*)(cb + (size_t)cA * DIMS);
    const float4* pb = (const float4*)(cb + (size_t)cB * DIMS);
    float a0 = 0.f, a1 = 0.f, a2 = 0.f, a3 = 0.f;
    float b0 = 0.f, b1 = 0.f, b2 = 0.f, b3 = 0.f;
    #pragma unroll
    for (int d = 0; d < DIMS; d += 4) {
        float x0 = xin[(d + 0) * HW], x1 = xin[(d + 1) * HW];
        float x2 = xin[(d + 2) * HW], x3 = xin[(d + 3) * HW];
        float4 va = pa[d / 4], vb = pb[d / 4];
        a0 = fmaf(x0, va.x, a0); a1 = fmaf(x1, va.y, a1);
        a2 = fmaf(x2, va.z, a2); a3 = fmaf(x3, va.w, a3);
        b0 = fmaf(x0, vb.x, b0); b1 = fmaf(x1, vb.y, b1);
        b2 = fmaf(x2, vb.z, b2); b3 = fmaf(x3, vb.w, b3);
    }
    const float* cnS = (const float*)(smem + SM_CN);
    float sA = fmaf(-2.f, (a0 + a1) + (a2 + a3), cnS[cA]);
    float sB = fmaf(-2.f, (b0 + b1) + (b2 + b3), cnS[cB]);
    int   fin = cA;
    float fs  = sA;
    if (sB < sA || (sB == sA && cB < cA)) { fin = cB; fs = sB; }

    // ---- gather chosen code row, scatter to [B,D,H,W] ----
    {
        const float4* cc = (const float4*)(cb + (size_t)fin * DIMS);
        float* o = out + (size_t)b * (DIMS * HW) + hw;
        #pragma unroll
        for (int i = 0; i < DIMS / 4; ++i) {
            float4 v = cc[i];
            o[(4 * i + 0) * HW] = v.x;
            o[(4 * i + 1) * HW] = v.y;
            o[(4 * i + 2) * HW] = v.z;
            o[(4 * i + 3) * HW] = v.w;
        }
    }

    // ---- loss partial (deterministic block tree) ----
    float* red = (float*)(smem + SM_RED);
    red[tid] = xnorm + fs;
    __syncthreads();
    #pragma unroll
    for (int s = THREADS / 2; s > 0; s >>= 1) {
        if (tid < s) red[tid] += red[tid + s];
        __syncthreads();
    }
    if (tid == 0) g_partial[blockIdx.x] = red[0];
}

// ---------------------------------------------------------------------------
__global__ void loss_kernel(float* __restrict__ out, int ndhw) {
    __shared__ float red[NBLOCKS];
    red[threadIdx.x] = g_partial[threadIdx.x];
    __syncthreads();
    #pragma unroll
    for (int s = NBLOCKS / 2; s > 0; s >>= 1) {
        if (threadIdx.x < s) red[threadIdx.x] += red[threadIdx.x + s];
        __syncthreads();
    }
    if (threadIdx.x == 0)
        out[ndhw] = 1.25f * red[0] / (float)ndhw;
}

// ---------------------------------------------------------------------------
extern "C" void kernel_launch(void* const* d_in, const int* in_sizes, int n_in,
                              void* d_out, int out_size) {
    const float* latents = (const float*)d_in[0];  // [64,64,32,32]
    const float* cb      = (const float*)d_in[1];  // [1024,64]
    float* out = (float*)d_out;
    const int ndhw = in_sizes[0];                  // 4194304

    static int smem_set = 0;
    if (!smem_set) {
        cudaFuncSetAttribute(vq_mma_kernel,
                             cudaFuncAttributeMaxDynamicSharedMemorySize, SM_TOTAL);
        smem_set = 1;
    }

    prep_kernel<<<64, 128>>>(cb);
    vq_mma_kernel<<<NBLOCKS, THREADS, SM_TOTAL>>>(latents, cb, out);
    loss_kernel<<<1, NBLOCKS>>>(out, ndhw);
}

// round 6
// speedup vs baseline: 1.4685x; 1.4685x over previous
#include <cuda_runtime.h>
#include <cuda_bf16.h>
#include <cstdint>

// VectorQuantizer via mma.sync.m16n8k16 bf16 (HMMA on sm_103):
// 3-term bf16-split GEMM distances, branchless quad-min top-2 argmin,
// exact fp32 re-rank. Round 6: round-4 skeleton + LDS.128 c-grouped
// fragments + quad-min epilogue (no branches, no launch_bounds cap).

#define DIMS    64
#define KCODES  1024
#define HW      1024
#define THREADS 128
#define NPOS    65536
#define NBLOCKS 512
#define PITCH   272                       // [hi 128B | lo 128B | pad 16B], 17x16B
#define TILE_CODES 128
#define TILE_BYTES (TILE_CODES * PITCH)   // 34816

// smem layout (round-4 style: A separate, 2 B buffers)
#define SM_A     0                        // 34816
#define SM_B0    34816
#define SM_B1    69632
#define SM_CN    104448                   // 1024 f32
#define SM_I1    108544                   // 128 int
#define SM_I2    109056                   // 128 int
#define SM_RED   109568                   // 128 f32
#define SM_TOTAL 110080

__device__ float g_cnorm[KCODES];
__device__ float g_partial[NBLOCKS];
__device__ __align__(16) unsigned char g_cb[KCODES * PITCH];

// Row layout (A and B, per 272B row): hi block [0,128), lo block [128,256).
// Lane-group c owns bytes [c*32, c*32+32) of each block; word w holds bf16
// dims (8w+2c, 8w+2c+1). One uint4 = k-steps 0,1; next uint4 = k-steps 2,3.

__device__ __forceinline__ uint32_t smem_u32(const void* p) {
    uint32_t a;
    asm("{ .reg .u64 t; cvta.to.shared.u64 t, %1; cvt.u32.u64 %0, t; }"
        : "=r"(a) : "l"(p));
    return a;
}

__device__ __forceinline__ uint32_t pack_bf16(float v0, float v1) {
    return (uint32_t)__bfloat16_as_ushort(__float2bfloat16(v0)) |
           ((uint32_t)__bfloat16_as_ushort(__float2bfloat16(v1)) << 16);
}

#define MMA(d, a, bb) \
    asm volatile("mma.sync.aligned.m16n8k16.row.col.f32.bf16.bf16.f32 " \
                 "{%0,%1,%2,%3}, {%4,%5,%6,%7}, {%8,%9}, {%0,%1,%2,%3};" \
                 : "+f"((d)[0]), "+f"((d)[1]), "+f"((d)[2]), "+f"((d)[3]) \
                 : "r"((a)[0]), "r"((a)[1]), "r"((a)[2]), "r"((a)[3]), \
                   "r"((bb)[0]), "r"((bb)[1]))

__device__ __forceinline__ void cpa16(uint32_t dst, const void* src) {
    asm volatile("cp.async.cg.shared.global [%0], [%1], 16;" :: "r"(dst), "l"(src));
}
#define CPA_COMMIT() asm volatile("cp.async.commit_group;" ::: "memory")
#define CPA_WAIT1()  asm volatile("cp.async.wait_group 1;" ::: "memory")

#define UPD(ri, s, ci) \
    do { if ((s) < best[ri]) { best2[ri] = best[ri]; i2[ri] = bidx[ri]; \
                               best[ri] = (s); bidx[ri] = (ci); } \
         else if ((s) < best2[ri]) { best2[ri] = (s); i2[ri] = (ci); } } while (0)

// ---------------------------------------------------------------------------
// Prep: 8 threads/code, c-grouped hi/lo layout + warp-reduced ||c||^2.
// ---------------------------------------------------------------------------
__global__ void prep_kernel(const float* __restrict__ cb) {
    const int idx = blockIdx.x * blockDim.x + threadIdx.x;   // 8192 threads
    const int k = idx >> 3;
    const int j = idx & 7;
    const float2* row = (const float2*)(cb + k * DIMS + j * 8);
    unsigned char* dst = g_cb + (size_t)k * PITCH;
    float cn = 0.f;
    #pragma unroll
    for (int c = 0; c < 4; ++c) {
        float2 v = row[c];                      // dims (8j+2c, 8j+2c+1)
        cn = fmaf(v.y, v.y, fmaf(v.x, v.x, cn));
        __nv_bfloat16 h0 = __float2bfloat16(v.x), h1 = __float2bfloat16(v.y);
        *(uint32_t*)(dst + c * 32 + j * 4) =
            (uint32_t)__bfloat16_as_ushort(h0) |
            ((uint32_t)__bfloat16_as_ushort(h1) << 16);
        *(uint32_t*)(dst + 128 + c * 32 + j * 4) =
            pack_bf16(v.x - __bfloat162float(h0), v.y - __bfloat162float(h1));
    }
    cn += __shfl_down_sync(0xffffffffu, cn, 4);
    cn += __shfl_down_sync(0xffffffffu, cn, 2);
    cn += __shfl_down_sync(0xffffffffu, cn, 1);
    if (j == 0) g_cnorm[k] = cn;
}

// ---------------------------------------------------------------------------
// Main kernel
// ---------------------------------------------------------------------------
__global__ __launch_bounds__(THREADS) void vq_mma_kernel(
    const float* __restrict__ latents,
    const float* __restrict__ cb,
    float* __restrict__ out)
{
    extern __shared__ unsigned char smem[];
    const uint32_t sb = smem_u32(smem);
    const int tid  = threadIdx.x;
    const int w    = tid >> 5;
    const int lane = tid & 31;
    const int g    = lane >> 2;
    const int c    = lane & 3;

    // prefetch B tiles 0 and 1
    #pragma unroll
    for (int i = 0; i < 17; ++i)
        cpa16(sb + SM_B0 + tid * 16 + i * 2048, g_cb + tid * 16 + i * 2048);
    CPA_COMMIT();
    #pragma unroll
    for (int i = 0; i < 17; ++i)
        cpa16(sb + SM_B1 + tid * 16 + i * 2048,
              g_cb + TILE_BYTES + tid * 16 + i * 2048);
    CPA_COMMIT();

    // cnorm -> smem
    #pragma unroll
    for (int i = tid; i < KCODES / 4; i += THREADS)
        ((float4*)(smem + SM_CN))[i] = ((const float4*)g_cnorm)[i];

    // ---- build A row (c-grouped hi/lo layout) ----
    const int p  = blockIdx.x * THREADS + tid;
    const int b  = p >> 10;
    const int hw = p & (HW - 1);
    const float* xin = latents + (size_t)b * (DIMS * HW) + hw;
    unsigned char* arow = smem + SM_A + tid * PITCH;
    float xn0 = 0.f, xn1 = 0.f;
    #pragma unroll
    for (int cc = 0; cc < 4; ++cc)
        #pragma unroll
        for (int ww = 0; ww < 8; ++ww) {
            const int d = 8 * ww + 2 * cc;
            float v0 = xin[d * HW], v1 = xin[(d + 1) * HW];
            xn0 = fmaf(v0, v0, xn0); xn1 = fmaf(v1, v1, xn1);
            __nv_bfloat16 h0 = __float2bfloat16(v0), h1 = __float2bfloat16(v1);
            *(uint32_t*)(arow + cc * 32 + ww * 4) =
                (uint32_t)__bfloat16_as_ushort(h0) |
                ((uint32_t)__bfloat16_as_ushort(h1) << 16);
            *(uint32_t*)(arow + 128 + cc * 32 + ww * 4) =
                pack_bf16(v0 - __bfloat162float(h0), v1 - __bfloat162float(h1));
        }
    const float xnorm = xn0 + xn1;
    __syncthreads();

    // ---- load A fragments (resident): 16x LDS.128 ----
    uint32_t aH[2][4][4], aL[2][4][4];
    const int rbase = 32 * w + g;
    #pragma unroll
    for (int mt = 0; mt < 2; ++mt) {
        const unsigned char* r0 = smem + SM_A + (rbase + 16 * mt) * PITCH + c * 32;
        const unsigned char* r8 = r0 + 8 * PITCH;
        #pragma unroll
        for (int half = 0; half < 2; ++half) {
            const int hb = half * 128;
            uint4 q0a = *(const uint4*)(r0 + hb);
            uint4 q0b = *(const uint4*)(r0 + hb + 16);
            uint4 q8a = *(const uint4*)(r8 + hb);
            uint4 q8b = *(const uint4*)(r8 + hb + 16);
            uint32_t (*A)[4][4] = half ? aL : aH;
            A[mt][0][0] = q0a.x; A[mt][0][2] = q0a.y;
            A[mt][1][0] = q0a.z; A[mt][1][2] = q0a.w;
            A[mt][2][0] = q0b.x; A[mt][2][2] = q0b.y;
            A[mt][3][0] = q0b.z; A[mt][3][2] = q0b.w;
            A[mt][0][1] = q8a.x; A[mt][0][3] = q8a.y;
            A[mt][1][1] = q8a.z; A[mt][1][3] = q8a.w;
            A[mt][2][1] = q8b.x; A[mt][2][3] = q8b.y;
            A[mt][3][1] = q8b.z; A[mt][3][3] = q8b.w;
        }
    }

    float best[4]  = {3.4e38f, 3.4e38f, 3.4e38f, 3.4e38f};
    float best2[4] = {3.4e38f, 3.4e38f, 3.4e38f, 3.4e38f};
    int   bidx[4]  = {0, 0, 0, 0};
    int   i2[4]    = {0, 0, 0, 0};

    #pragma unroll 1
    for (int tb = 0; tb < 8; ++tb) {
        CPA_WAIT1();
        __syncthreads();
        const unsigned char* bbuf = smem + SM_B0 + (tb & 1) * TILE_BYTES;

        #pragma unroll 1
        for (int np = 0; np < 8; ++np) {
            // B fragments: 8x LDS.128
            uint32_t bH[2][4][2], bL[2][4][2];
            #pragma unroll
            for (int j = 0; j < 2; ++j) {
                const unsigned char* rb =
                    bbuf + ((2 * np + j) * 8 + g) * PITCH + c * 32;
                uint4 h0 = *(const uint4*)(rb);
                uint4 h1 = *(const uint4*)(rb + 16);
                uint4 l0 = *(const uint4*)(rb + 128);
                uint4 l1 = *(const uint4*)(rb + 144);
                bH[j][0][0] = h0.x; bH[j][0][1] = h0.y;
                bH[j][1][0] = h0.z; bH[j][1][1] = h0.w;
                bH[j][2][0] = h1.x; bH[j][2][1] = h1.y;
                bH[j][3][0] = h1.z; bH[j][3][1] = h1.w;
                bL[j][0][0] = l0.x; bL[j][0][1] = l0.y;
                bL[j][1][0] = l0.z; bL[j][1][1] = l0.w;
                bL[j][2][0] = l1.x; bL[j][2][1] = l1.y;
                bL[j][3][0] = l1.z; bL[j][3][1] = l1.w;
            }
            float D[2][2][4];
            #pragma unroll
            for (int j = 0; j < 2; ++j)
                #pragma unroll
                for (int mt = 0; mt < 2; ++mt)
                    #pragma unroll
                    for (int q = 0; q < 4; ++q) D[j][mt][q] = 0.f;

            #pragma unroll
            for (int kt = 0; kt < 4; ++kt) {
                MMA(D[0][0], aH[0][kt], bH[0][kt]);
                MMA(D[0][1], aH[1][kt], bH[0][kt]);
                MMA(D[1][0], aH[0][kt], bH[1][kt]);
                MMA(D[1][1], aH[1][kt], bH[1][kt]);
                MMA(D[0][0], aL[0][kt], bH[0][kt]);
                MMA(D[0][1], aL[1][kt], bH[0][kt]);
                MMA(D[1][0], aL[0][kt], bH[1][kt]);
                MMA(D[1][1], aL[1][kt], bH[1][kt]);
                MMA(D[0][0], aH[0][kt], bL[0][kt]);
                MMA(D[0][1], aH[1][kt], bL[0][kt]);
                MMA(D[1][0], aH[0][kt], bL[1][kt]);
                MMA(D[1][1], aH[1][kt], bL[1][kt]);
            }

            // ---- branchless quad-min top-2 epilogue ----
            const int cb0 = tb * 128 + (2 * np) * 8 + 2 * c;
            const int cb1 = cb0 + 8;
            const float2 cnA = *(const float2*)(smem + SM_CN + cb0 * 4);
            const float2 cnB = *(const float2*)(smem + SM_CN + cb1 * 4);
            #pragma unroll
            for (int mt = 0; mt < 2; ++mt)
                #pragma unroll
                for (int rr = 0; rr < 2; ++rr) {
                    const int r = 2 * mt + rr;
                    float s0 = fmaf(-2.f, D[0][mt][2 * rr + 0], cnA.x);
                    float s1 = fmaf(-2.f, D[0][mt][2 * rr + 1], cnA.y);
                    float s2 = fmaf(-2.f, D[1][mt][2 * rr + 0], cnB.x);
                    float s3 = fmaf(-2.f, D[1][mt][2 * rr + 1], cnB.y);
                    float m = fminf(fminf(s0, s1), fminf(s2, s3));
                    // lowest column among equals (ascending select order)
                    int col = (m == s2) ? cb1 : cb1 + 1;
                    col = (m == s1) ? cb0 + 1 : col;
                    col = (m == s0) ? cb0 : col;
                    UPD(r, m, col);
                }
        }

        __syncthreads();   // all readers done with buf[tb&1]
        if (tb + 2 < 8) {
            const uint32_t bdst = sb + SM_B0 + (tb & 1) * TILE_BYTES;
            #pragma unroll
            for (int i = 0; i < 17; ++i)
                cpa16(bdst + tid * 16 + i * 2048,
                      g_cb + (size_t)(tb + 2) * TILE_BYTES + tid * 16 + i * 2048);
        }
        CPA_COMMIT();      // empty group when no prefetch -> uniform accounting
    }

    // ---- merge top-2 across the 4 lanes (c) sharing each row ----
    #pragma unroll
    for (int m = 1; m <= 2; m <<= 1) {
        #pragma unroll
        for (int r = 0; r < 4; ++r) {
            float ob  = __shfl_xor_sync(0xffffffffu, best[r], m);
            int   oi  = __shfl_xor_sync(0xffffffffu, bidx[r], m);
            float ob2 = __shfl_xor_sync(0xffffffffu, best2[r], m);
            int   oi2 = __shfl_xor_sync(0xffffffffu, i2[r], m);
            bool ow = (ob < best[r]) || (ob == best[r] && oi < bidx[r]);
            float nb  = ow ? ob : best[r];  int nbi = ow ? oi : bidx[r];
            float c1  = ow ? best[r] : ob;  int c1i = ow ? bidx[r] : oi;
            float c2  = ow ? ob2 : best2[r]; int c2i = ow ? oi2 : i2[r];
            bool s2 = (c2 < c1) || (c2 == c1 && c2i < c1i);
            best[r] = nb; bidx[r] = nbi;
            best2[r] = s2 ? c2 : c1; i2[r] = s2 ? c2i : c1i;
        }
    }
    int* sI1 = (int*)(smem + SM_I1);
    int* sI2 = (int*)(smem + SM_I2);
    if (c == 0) {
        #pragma unroll
        for (int r = 0; r < 4; ++r) {
            sI1[rbase + 8 * r] = bidx[r];
            sI2[rbase + 8 * r] = i2[r];
        }
    }
    __syncthreads();

    // ---- exact fp32 re-rank of the 2 candidates ----
    const int cA = sI1[tid], cB = sI2[tid];
    const float4* pa = (const float4*)(cb + (size_t)cA * DIMS);
    const float4* pb = (const float4*)(cb + (size_t)cB * DIMS);
    float a0 = 0.f, a1 = 0.f, a2 = 0.f, a3 = 0.f;
    float b0 = 0.f, b1 = 0.f, b2 = 0.f, b3 = 0.f;
    #pragma unroll
    for (int d = 0; d < DIMS; d += 4) {
        float x0 = xin[(d + 0) * HW], x1 = xin[(d + 1) * HW];
        float x2 = xin[(d + 2) * HW], x3 = xin[(d + 3) * HW];
        float4 va = pa[d / 4], vb = pb[d / 4];
        a0 = fmaf(x0, va.x, a0); a1 = fmaf(x1, va.y, a1);
        a2 = fmaf(x2, va.z, a2); a3 = fmaf(x3, va.w, a3);
        b0 = fmaf(x0, vb.x, b0); b1 = fmaf(x1, vb.y, b1);
        b2 = fmaf(x2, vb.z, b2); b3 = fmaf(x3, vb.w, b3);
    }
    const float* cnS = (const float*)(smem + SM_CN);
    float sA = fmaf(-2.f, (a0 + a1) + (a2 + a3), cnS[cA]);
    float sB = fmaf(-2.f, (b0 + b1) + (b2 + b3), cnS[cB]);
    int   fin = cA;
    float fs  = sA;
    if (sB < sA || (sB == sA && cB < cA)) { fin = cB; fs = sB; }

    // ---- gather chosen code row, scatter to [B,D,H,W] ----
    {
        const float4* cc = (const float4*)(cb + (size_t)fin * DIMS);
        float* o = out + (size_t)b * (DIMS * HW) + hw;
        #pragma unroll
        for (int i = 0; i < DIMS / 4; ++i) {
            float4 v = cc[i];
            o[(4 * i + 0) * HW] = v.x;
            o[(4 * i + 1) * HW] = v.y;
            o[(4 * i + 2) * HW] = v.z;
            o[(4 * i + 3) * HW] = v.w;
        }
    }

    // ---- loss partial (deterministic block tree) ----
    float* red = (float*)(smem + SM_RED);
    red[tid] = xnorm + fs;
    __syncthreads();
    #pragma unroll
    for (int s = THREADS / 2; s > 0; s >>= 1) {
        if (tid < s) red[tid] += red[tid + s];
        __syncthreads();
    }
    if (tid == 0) g_partial[blockIdx.x] = red[0];
}

// ---------------------------------------------------------------------------
__global__ void loss_kernel(float* __restrict__ out, int ndhw) {
    __shared__ float red[NBLOCKS];
    red[threadIdx.x] = g_partial[threadIdx.x];
    __syncthreads();
    #pragma unroll
    for (int s = NBLOCKS / 2; s > 0; s >>= 1) {
        if (threadIdx.x < s) red[threadIdx.x] += red[threadIdx.x + s];
        __syncthreads();
    }
    if (threadIdx.x == 0)
        out[ndhw] = 1.25f * red[0] / (float)ndhw;
}

// ---------------------------------------------------------------------------
extern "C" void kernel_launch(void* const* d_in, const int* in_sizes, int n_in,
                              void* d_out, int out_size) {
    const float* latents = (const float*)d_in[0];  // [64,64,32,32]
    const float* cb      = (const float*)d_in[1];  // [1024,64]
    float* out = (float*)d_out;
    const int ndhw = in_sizes[0];                  // 4194304

    static int smem_set = 0;
    if (!smem_set) {
        cudaFuncSetAttribute(vq_mma_kernel,
                             cudaFuncAttributeMaxDynamicSharedMemorySize, SM_TOTAL);
        smem_set = 1;
    }

    prep_kernel<<<64, 128>>>(cb);
    vq_mma_kernel<<<NBLOCKS, THREADS, SM_TOTAL>>>(latents, cb, out);
    loss_kernel<<<1, NBLOCKS>>>(out, ndhw);
}

// round 8
// speedup vs baseline: 1.5303x; 1.0421x over previous
#include <cuda_runtime.h>
#include <cuda_bf16.h>
#include <cstdint>

// VectorQuantizer via mma.sync.m16n8k16 bf16 (HMMA on sm_103):
// 3-term bf16-split GEMM distances, branchless quad-min top-2 argmin,
// exact fp32 re-rank. Round 8: half-tile B streaming -> 73.5 KB smem ->
// 3 CTAs/SM (3 warps/SMSP) to cover HMMA/LDS latency.

#define DIMS    64
#define KCODES  1024
#define HW      1024
#define THREADS 128
#define NPOS    65536
#define NBLOCKS 512
#define PITCH   272                       // [hi 128B | lo 128B | pad 16B], 17x16B
#define HT_CODES 64
#define HT_BYTES (HT_CODES * PITCH)       // 17408
#define NHT      16                       // 16 half-tiles of 64 codes

// smem layout
#define SM_A     0                        // 34816
#define SM_H0    34816                    // 17408
#define SM_H1    52224                    // 17408
#define SM_CN    69632                    // 1024 f32
#define SM_I1    73728                    // 128 int
#define SM_I2    74240                    // 128 int
#define SM_RED   74752                    // 128 f32
#define SM_TOTAL 75264

__device__ float g_cnorm[KCODES];
__device__ float g_partial[NBLOCKS];
__device__ __align__(16) unsigned char g_cb[KCODES * PITCH];

// Row layout (A and B, per 272B row): hi block [0,128), lo block [128,256).
// Lane-group c owns bytes [c*32, c*32+32) of each block; word w holds bf16
// dims (8w+2c, 8w+2c+1). One uint4 = k-steps 0,1; next uint4 = k-steps 2,3.

__device__ __forceinline__ uint32_t smem_u32(const void* p) {
    uint32_t a;
    asm("{ .reg .u64 t; cvta.to.shared.u64 t, %1; cvt.u32.u64 %0, t; }"
        : "=r"(a) : "l"(p));
    return a;
}

__device__ __forceinline__ uint32_t pack_bf16(float v0, float v1) {
    return (uint32_t)__bfloat16_as_ushort(__float2bfloat16(v0)) |
           ((uint32_t)__bfloat16_as_ushort(__float2bfloat16(v1)) << 16);
}

#define MMA(d, a, bb) \
    asm volatile("mma.sync.aligned.m16n8k16.row.col.f32.bf16.bf16.f32 " \
                 "{%0,%1,%2,%3}, {%4,%5,%6,%7}, {%8,%9}, {%0,%1,%2,%3};" \
                 : "+f"((d)[0]), "+f"((d)[1]), "+f"((d)[2]), "+f"((d)[3]) \
                 : "r"((a)[0]), "r"((a)[1]), "r"((a)[2]), "r"((a)[3]), \
                   "r"((bb)[0]), "r"((bb)[1]))

__device__ __forceinline__ void cpa16(uint32_t dst, const void* src) {
    asm volatile("cp.async.cg.shared.global [%0], [%1], 16;" :: "r"(dst), "l"(src));
}
#define CPA_COMMIT() asm volatile("cp.async.commit_group;" ::: "memory")
#define CPA_WAIT1()  asm volatile("cp.async.wait_group 1;" ::: "memory")

#define UPD(ri, s, ci) \
    do { if ((s) < best[ri]) { best2[ri] = best[ri]; i2[ri] = bidx[ri]; \
                               best[ri] = (s); bidx[ri] = (ci); } \
         else if ((s) < best2[ri]) { best2[ri] = (s); i2[ri] = (ci); } } while (0)

// copy one 64-code half-tile (17408 B) gmem -> smem via cp.async
__device__ __forceinline__ void prefetch_ht(uint32_t sdst, const unsigned char* src,
                                            int tid) {
    #pragma unroll
    for (int i = 0; i < 8; ++i)
        cpa16(sdst + tid * 16 + i * 2048, src + tid * 16 + i * 2048);
    if (tid < 64)
        cpa16(sdst + 16384 + tid * 16, src + 16384 + tid * 16);
}

// ---------------------------------------------------------------------------
// Prep: 8 threads/code, c-grouped hi/lo layout + warp-reduced ||c||^2.
// ---------------------------------------------------------------------------
__global__ void prep_kernel(const float* __restrict__ cb) {
    const int idx = blockIdx.x * blockDim.x + threadIdx.x;   // 8192 threads
    const int k = idx >> 3;
    const int j = idx & 7;
    const float2* row = (const float2*)(cb + k * DIMS + j * 8);
    unsigned char* dst = g_cb + (size_t)k * PITCH;
    float cn = 0.f;
    #pragma unroll
    for (int c = 0; c < 4; ++c) {
        float2 v = row[c];                      // dims (8j+2c, 8j+2c+1)
        cn = fmaf(v.y, v.y, fmaf(v.x, v.x, cn));
        __nv_bfloat16 h0 = __float2bfloat16(v.x), h1 = __float2bfloat16(v.y);
        *(uint32_t*)(dst + c * 32 + j * 4) =
            (uint32_t)__bfloat16_as_ushort(h0) |
            ((uint32_t)__bfloat16_as_ushort(h1) << 16);
        *(uint32_t*)(dst + 128 + c * 32 + j * 4) =
            pack_bf16(v.x - __bfloat162float(h0), v.y - __bfloat162float(h1));
    }
    cn += __shfl_down_sync(0xffffffffu, cn, 4);
    cn += __shfl_down_sync(0xffffffffu, cn, 2);
    cn += __shfl_down_sync(0xffffffffu, cn, 1);
    if (j == 0) g_cnorm[k] = cn;
}

// ---------------------------------------------------------------------------
// Main kernel
// ---------------------------------------------------------------------------
__global__ __launch_bounds__(THREADS, 3) void vq_mma_kernel(
    const float* __restrict__ latents,
    const float* __restrict__ cb,
    float* __restrict__ out)
{
    extern __shared__ unsigned char smem[];
    const uint32_t sb = smem_u32(smem);
    const int tid  = threadIdx.x;
    const int w    = tid >> 5;
    const int lane = tid & 31;
    const int g    = lane >> 2;
    const int c    = lane & 3;

    // prefetch half-tiles 0 and 1
    prefetch_ht(sb + SM_H0, g_cb, tid);
    CPA_COMMIT();
    prefetch_ht(sb + SM_H1, g_cb + HT_BYTES, tid);
    CPA_COMMIT();

    // cnorm -> smem
    #pragma unroll
    for (int i = tid; i < KCODES / 4; i += THREADS)
        ((float4*)(smem + SM_CN))[i] = ((const float4*)g_cnorm)[i];

    // ---- build A row (c-grouped hi/lo layout) ----
    const int p  = blockIdx.x * THREADS + tid;
    const int b  = p >> 10;
    const int hw = p & (HW - 1);
    const float* xin = latents + (size_t)b * (DIMS * HW) + hw;
    unsigned char* arow = smem + SM_A + tid * PITCH;
    float xn0 = 0.f, xn1 = 0.f;
    #pragma unroll
    for (int cc = 0; cc < 4; ++cc)
        #pragma unroll
        for (int ww = 0; ww < 8; ++ww) {
            const int d = 8 * ww + 2 * cc;
            float v0 = xin[d * HW], v1 = xin[(d + 1) * HW];
            xn0 = fmaf(v0, v0, xn0); xn1 = fmaf(v1, v1, xn1);
            __nv_bfloat16 h0 = __float2bfloat16(v0), h1 = __float2bfloat16(v1);
            *(uint32_t*)(arow + cc * 32 + ww * 4) =
                (uint32_t)__bfloat16_as_ushort(h0) |
                ((uint32_t)__bfloat16_as_ushort(h1) << 16);
            *(uint32_t*)(arow + 128 + cc * 32 + ww * 4) =
                pack_bf16(v0 - __bfloat162float(h0), v1 - __bfloat162float(h1));
        }
    const float xnorm = xn0 + xn1;
    __syncthreads();

    // ---- load A fragments (resident): 16x LDS.128 ----
    uint32_t aH[2][4][4], aL[2][4][4];
    const int rbase = 32 * w + g;
    #pragma unroll
    for (int mt = 0; mt < 2; ++mt) {
        const unsigned char* r0 = smem + SM_A + (rbase + 16 * mt) * PITCH + c * 32;
        const unsigned char* r8 = r0 + 8 * PITCH;
        #pragma unroll
        for (int half = 0; half < 2; ++half) {
            const int hb = half * 128;
            uint4 q0a = *(const uint4*)(r0 + hb);
            uint4 q0b = *(const uint4*)(r0 + hb + 16);
            uint4 q8a = *(const uint4*)(r8 + hb);
            uint4 q8b = *(const uint4*)(r8 + hb + 16);
            uint32_t (*A)[4][4] = half ? aL : aH;
            A[mt][0][0] = q0a.x; A[mt][0][2] = q0a.y;
            A[mt][1][0] = q0a.z; A[mt][1][2] = q0a.w;
            A[mt][2][0] = q0b.x; A[mt][2][2] = q0b.y;
            A[mt][3][0] = q0b.z; A[mt][3][2] = q0b.w;
            A[mt][0][1] = q8a.x; A[mt][0][3] = q8a.y;
            A[mt][1][1] = q8a.z; A[mt][1][3] = q8a.w;
            A[mt][2][1] = q8b.x; A[mt][2][3] = q8b.y;
            A[mt][3][1] = q8b.z; A[mt][3][3] = q8b.w;
        }
    }

    float best[4]  = {3.4e38f, 3.4e38f, 3.4e38f, 3.4e38f};
    float best2[4] = {3.4e38f, 3.4e38f, 3.4e38f, 3.4e38f};
    int   bidx[4]  = {0, 0, 0, 0};
    int   i2[4]    = {0, 0, 0, 0};

    #pragma unroll 1
    for (int ht = 0; ht < NHT; ++ht) {
        CPA_WAIT1();
        __syncthreads();
        const unsigned char* bbuf = smem + SM_H0 + (ht & 1) * HT_BYTES;

        #pragma unroll 1
        for (int np = 0; np < 4; ++np) {
            // B fragments: 8x LDS.128
            uint32_t bH[2][4][2], bL[2][4][2];
            #pragma unroll
            for (int j = 0; j < 2; ++j) {
                const unsigned char* rb =
                    bbuf + ((2 * np + j) * 8 + g) * PITCH + c * 32;
                uint4 h0 = *(const uint4*)(rb);
                uint4 h1 = *(const uint4*)(rb + 16);
                uint4 l0 = *(const uint4*)(rb + 128);
                uint4 l1 = *(const uint4*)(rb + 144);
                bH[j][0][0] = h0.x; bH[j][0][1] = h0.y;
                bH[j][1][0] = h0.z; bH[j][1][1] = h0.w;
                bH[j][2][0] = h1.x; bH[j][2][1] = h1.y;
                bH[j][3][0] = h1.z; bH[j][3][1] = h1.w;
                bL[j][0][0] = l0.x; bL[j][0][1] = l0.y;
                bL[j][1][0] = l0.z; bL[j][1][1] = l0.w;
                bL[j][2][0] = l1.x; bL[j][2][1] = l1.y;
                bL[j][3][0] = l1.z; bL[j][3][1] = l1.w;
            }
            float D[2][2][4];
            #pragma unroll
            for (int j = 0; j < 2; ++j)
                #pragma unroll
                for (int mt = 0; mt < 2; ++mt)
                    #pragma unroll
                    for (int q = 0; q < 4; ++q) D[j][mt][q] = 0.f;

            #pragma unroll
            for (int kt = 0; kt < 4; ++kt) {
                MMA(D[0][0], aH[0][kt], bH[0][kt]);
                MMA(D[0][1], aH[1][kt], bH[0][kt]);
                MMA(D[1][0], aH[0][kt], bH[1][kt]);
                MMA(D[1][1], aH[1][kt], bH[1][kt]);
                MMA(D[0][0], aL[0][kt], bH[0][kt]);
                MMA(D[0][1], aL[1][kt], bH[0][kt]);
                MMA(D[1][0], aL[0][kt], bH[1][kt]);
                MMA(D[1][1], aL[1][kt], bH[1][kt]);
                MMA(D[0][0], aH[0][kt], bL[0][kt]);
                MMA(D[0][1], aH[1][kt], bL[0][kt]);
                MMA(D[1][0], aH[0][kt], bL[1][kt]);
                MMA(D[1][1], aH[1][kt], bL[1][kt]);
            }

            // ---- branchless quad-min top-2 epilogue ----
            const int cb0 = ht * HT_CODES + (2 * np) * 8 + 2 * c;
            const int cb1 = cb0 + 8;
            const float2 cnA = *(const float2*)(smem + SM_CN + cb0 * 4);
            const float2 cnB = *(const float2*)(smem + SM_CN + cb1 * 4);
            #pragma unroll
            for (int mt = 0; mt < 2; ++mt)
                #pragma unroll
                for (int rr = 0; rr < 2; ++rr) {
                    const int r = 2 * mt + rr;
                    float s0 = fmaf(-2.f, D[0][mt][2 * rr + 0], cnA.x);
                    float s1 = fmaf(-2.f, D[0][mt][2 * rr + 1], cnA.y);
                    float s2 = fmaf(-2.f, D[1][mt][2 * rr + 0], cnB.x);
                    float s3 = fmaf(-2.f, D[1][mt][2 * rr + 1], cnB.y);
                    float m = fminf(fminf(s0, s1), fminf(s2, s3));
                    int col = (m == s2) ? cb1 : cb1 + 1;
                    col = (m == s1) ? cb0 + 1 : col;
                    col = (m == s0) ? cb0 : col;
                    UPD(r, m, col);
                }
        }

        __syncthreads();   // all readers done with buf[ht&1]
        if (ht + 2 < NHT)
            prefetch_ht(sb + SM_H0 + (ht & 1) * HT_BYTES,
                        g_cb + (size_t)(ht + 2) * HT_BYTES, tid);
        CPA_COMMIT();      // empty group when no prefetch -> uniform accounting
    }

    // ---- merge top-2 across the 4 lanes (c) sharing each row ----
    #pragma unroll
    for (int m = 1; m <= 2; m <<= 1) {
        #pragma unroll
        for (int r = 0; r < 4; ++r) {
            float ob  = __shfl_xor_sync(0xffffffffu, best[r], m);
            int   oi  = __shfl_xor_sync(0xffffffffu, bidx[r], m);
            float ob2 = __shfl_xor_sync(0xffffffffu, best2[r], m);
            int   oi2 = __shfl_xor_sync(0xffffffffu, i2[r], m);
            bool ow = (ob < best[r]) || (ob == best[r] && oi < bidx[r]);
            float nb  = ow ? ob : best[r];  int nbi = ow ? oi : bidx[r];
            float c1  = ow ? best[r] : ob;  int c1i = ow ? bidx[r] : oi;
            float c2  = ow ? ob2 : best2[r]; int c2i = ow ? oi2 : i2[r];
            bool s2 = (c2 < c1) || (c2 == c1 && c2i < c1i);
            best[r] = nb; bidx[r] = nbi;
            best2[r] = s2 ? c2 : c1; i2[r] = s2 ? c2i : c1i;
        }
    }
    int* sI1 = (int*)(smem + SM_I1);
    int* sI2 = (int*)(smem + SM_I2);
    if (c == 0) {
        #pragma unroll
        for (int r = 0; r < 4; ++r) {
            sI1[rbase + 8 * r] = bidx[r];
            sI2[rbase + 8 * r] = i2[r];
        }
    }
    __syncthreads();

    // ---- exact fp32 re-rank of the 2 candidates ----
    const int cA = sI1[tid], cB = sI2[tid];
    const float4* pa = (const float4*)(cb + (size_t)cA * DIMS);
    const float4* pb = (const float4*)(cb + (size_t)cB * DIMS);
    float a0 = 0.f, a1 = 0.f, a2 = 0.f, a3 = 0.f;
    float b0 = 0.f, b1 = 0.f, b2 = 0.f, b3 = 0.f;
    #pragma unroll
    for (int d = 0; d < DIMS; d += 4) {
        float x0 = xin[(d + 0) * HW], x1 = xin[(d + 1) * HW];
        float x2 = xin[(d + 2) * HW], x3 = xin[(d + 3) * HW];
        float4 va = pa[d / 4], vb = pb[d / 4];
        a0 = fmaf(x0, va.x, a0); a1 = fmaf(x1, va.y, a1);
        a2 = fmaf(x2, va.z, a2); a3 = fmaf(x3, va.w, a3);
        b0 = fmaf(x0, vb.x, b0); b1 = fmaf(x1, vb.y, b1);
        b2 = fmaf(x2, vb.z, b2); b3 = fmaf(x3, vb.w, b3);
    }
    const float* cnS = (const float*)(smem + SM_CN);
    float sA = fmaf(-2.f, (a0 + a1) + (a2 + a3), cnS[cA]);
    float sB = fmaf(-2.f, (b0 + b1) + (b2 + b3), cnS[cB]);
    int   fin = cA;
    float fs  = sA;
    if (sB < sA || (sB == sA && cB < cA)) { fin = cB; fs = sB; }

    // ---- gather chosen code row, scatter to [B,D,H,W] ----
    {
        const float4* cc = (const float4*)(cb + (size_t)fin * DIMS);
        float* o = out + (size_t)b * (DIMS * HW) + hw;
        #pragma unroll
        for (int i = 0; i < DIMS / 4; ++i) {
            float4 v = cc[i];
            o[(4 * i + 0) * HW] = v.x;
            o[(4 * i + 1) * HW] = v.y;
            o[(4 * i + 2) * HW] = v.z;
            o[(4 * i + 3) * HW] = v.w;
        }
    }

    // ---- loss partial (deterministic block tree) ----
    float* red = (float*)(smem + SM_RED);
    red[tid] = xnorm + fs;
    __syncthreads();
    #pragma unroll
    for (int s = THREADS / 2; s > 0; s >>= 1) {
        if (tid < s) red[tid] += red[tid + s];
        __syncthreads();
    }
    if (tid == 0) g_partial[blockIdx.x] = red[0];
}

// ---------------------------------------------------------------------------
__global__ void loss_kernel(float* __restrict__ out, int ndhw) {
    __shared__ float red[NBLOCKS];
    red[threadIdx.x] = g_partial[threadIdx.x];
    __syncthreads();
    #pragma unroll
    for (int s = NBLOCKS / 2; s > 0; s >>= 1) {
        if (threadIdx.x < s) red[threadIdx.x] += red[threadIdx.x + s];
        __syncthreads();
    }
    if (threadIdx.x == 0)
        out[ndhw] = 1.25f * red[0] / (float)ndhw;
}

// ---------------------------------------------------------------------------
extern "C" void kernel_launch(void* const* d_in, const int* in_sizes, int n_in,
                              void* d_out, int out_size) {
    const float* latents = (const float*)d_in[0];  // [64,64,32,32]
    const float* cb      = (const float*)d_in[1];  // [1024,64]
    float* out = (float*)d_out;
    const int ndhw = in_sizes[0];                  // 4194304

    static int smem_set = 0;
    if (!smem_set) {
        cudaFuncSetAttribute(vq_mma_kernel,
                             cudaFuncAttributeMaxDynamicSharedMemorySize, SM_TOTAL);
        smem_set = 1;
    }

    prep_kernel<<<64, 128>>>(cb);
    vq_mma_kernel<<<NBLOCKS, THREADS, SM_TOTAL>>>(latents, cb, out);
    loss_kernel<<<1, NBLOCKS>>>(out, ndhw);
}

// round 9
// speedup vs baseline: 1.5394x; 1.0059x over previous
#include <cuda_runtime.h>
#include <cuda_bf16.h>
#include <cstdint>

// VectorQuantizer via mma.sync.m16n8k16 bf16 (HMMA on sm_103):
// 3-term bf16-split GEMM distances, branchless quad-min top-2 argmin,
// exact fp32 re-rank. Round 9: 64 positions/CTA (1024 CTAs) to kill the
// ragged tail wave; 56.5 KB smem + small regs -> 4 CTAs/SM.

#define DIMS    64
#define KCODES  1024
#define HW      1024
#define THREADS 128
#define NPOS    65536
#define POSC    64                        // positions per CTA
#define NBLOCKS (NPOS / POSC)             // 1024
#define PITCH   272                       // [hi 128B | lo 128B | pad 16B]
#define HT_CODES 64
#define HT_BYTES (HT_CODES * PITCH)       // 17408
#define NHT      16

// smem layout
#define SM_A     0                        // 64 x 272 = 17408
#define SM_H0    17408
#define SM_H1    34816
#define SM_CN    52224                    // 1024 f32
#define SM_I1    56320                    // 64 int (pad to 512)
#define SM_I2    56832
#define SM_RED   57344                    // 128 f32
#define SM_TOTAL 57856

__device__ float g_cnorm[KCODES];
__device__ float g_partial[NBLOCKS];
__device__ __align__(16) unsigned char g_cb[KCODES * PITCH];

__device__ __forceinline__ uint32_t smem_u32(const void* p) {
    uint32_t a;
    asm("{ .reg .u64 t; cvta.to.shared.u64 t, %1; cvt.u32.u64 %0, t; }"
        : "=r"(a) : "l"(p));
    return a;
}

__device__ __forceinline__ uint32_t pack_bf16(float v0, float v1) {
    return (uint32_t)__bfloat16_as_ushort(__float2bfloat16(v0)) |
           ((uint32_t)__bfloat16_as_ushort(__float2bfloat16(v1)) << 16);
}

#define MMA(d, a, bb) \
    asm volatile("mma.sync.aligned.m16n8k16.row.col.f32.bf16.bf16.f32 " \
                 "{%0,%1,%2,%3}, {%4,%5,%6,%7}, {%8,%9}, {%0,%1,%2,%3};" \
                 : "+f"((d)[0]), "+f"((d)[1]), "+f"((d)[2]), "+f"((d)[3]) \
                 : "r"((a)[0]), "r"((a)[1]), "r"((a)[2]), "r"((a)[3]), \
                   "r"((bb)[0]), "r"((bb)[1]))

__device__ __forceinline__ void cpa16(uint32_t dst, const void* src) {
    asm volatile("cp.async.cg.shared.global [%0], [%1], 16;" :: "r"(dst), "l"(src));
}
#define CPA_COMMIT() asm volatile("cp.async.commit_group;" ::: "memory")
#define CPA_WAIT1()  asm volatile("cp.async.wait_group 1;" ::: "memory")

#define UPD(ri, s, ci) \
    do { if ((s) < best[ri]) { best2[ri] = best[ri]; i2[ri] = bidx[ri]; \
                               best[ri] = (s); bidx[ri] = (ci); } \
         else if ((s) < best2[ri]) { best2[ri] = (s); i2[ri] = (ci); } } while (0)

// copy one 64-code half-tile (17408 B) gmem -> smem via cp.async
__device__ __forceinline__ void prefetch_ht(uint32_t sdst, const unsigned char* src,
                                            int tid) {
    #pragma unroll
    for (int i = 0; i < 8; ++i)
        cpa16(sdst + tid * 16 + i * 2048, src + tid * 16 + i * 2048);
    if (tid < 64)
        cpa16(sdst + 16384 + tid * 16, src + 16384 + tid * 16);
}

// ---------------------------------------------------------------------------
// Prep: 8 threads/code, c-grouped hi/lo layout + warp-reduced ||c||^2.
// ---------------------------------------------------------------------------
__global__ void prep_kernel(const float* __restrict__ cb) {
    const int idx = blockIdx.x * blockDim.x + threadIdx.x;   // 8192 threads
    const int k = idx >> 3;
    const int j = idx & 7;
    const float2* row = (const float2*)(cb + k * DIMS + j * 8);
    unsigned char* dst = g_cb + (size_t)k * PITCH;
    float cn = 0.f;
    #pragma unroll
    for (int c = 0; c < 4; ++c) {
        float2 v = row[c];                      // dims (8j+2c, 8j+2c+1)
        cn = fmaf(v.y, v.y, fmaf(v.x, v.x, cn));
        __nv_bfloat16 h0 = __float2bfloat16(v.x), h1 = __float2bfloat16(v.y);
        *(uint32_t*)(dst + c * 32 + j * 4) =
            (uint32_t)__bfloat16_as_ushort(h0) |
            ((uint32_t)__bfloat16_as_ushort(h1) << 16);
        *(uint32_t*)(dst + 128 + c * 32 + j * 4) =
            pack_bf16(v.x - __bfloat162float(h0), v.y - __bfloat162float(h1));
    }
    cn += __shfl_down_sync(0xffffffffu, cn, 4);
    cn += __shfl_down_sync(0xffffffffu, cn, 2);
    cn += __shfl_down_sync(0xffffffffu, cn, 1);
    if (j == 0) g_cnorm[k] = cn;
}

// ---------------------------------------------------------------------------
// Main kernel: 64 positions per CTA
// ---------------------------------------------------------------------------
__global__ __launch_bounds__(THREADS, 4) void vq_mma_kernel(
    const float* __restrict__ latents,
    const float* __restrict__ cb,
    float* __restrict__ out)
{
    extern __shared__ unsigned char smem[];
    const uint32_t sb = smem_u32(smem);
    const int tid  = threadIdx.x;
    const int w    = tid >> 5;
    const int lane = tid & 31;
    const int g    = lane >> 2;
    const int c    = lane & 3;

    // prefetch half-tiles 0 and 1
    prefetch_ht(sb + SM_H0, g_cb, tid);
    CPA_COMMIT();
    prefetch_ht(sb + SM_H1, g_cb + HT_BYTES, tid);
    CPA_COMMIT();

    // cnorm -> smem
    #pragma unroll
    for (int i = tid; i < KCODES / 4; i += THREADS)
        ((float4*)(smem + SM_CN))[i] = ((const float4*)g_cnorm)[i];

    // ---- build A rows (tid < 64: one position each) ----
    const int prow = tid & 63;                     // row/position within CTA
    const int p  = blockIdx.x * POSC + prow;
    const int b  = p >> 10;
    const int hw = p & (HW - 1);
    const float* xin = latents + (size_t)b * (DIMS * HW) + hw;
    float xnorm = 0.f;
    if (tid < POSC) {
        unsigned char* arow = smem + SM_A + tid * PITCH;
        float xn0 = 0.f, xn1 = 0.f;
        #pragma unroll
        for (int cc = 0; cc < 4; ++cc)
            #pragma unroll
            for (int ww = 0; ww < 8; ++ww) {
                const int d = 8 * ww + 2 * cc;
                float v0 = xin[d * HW], v1 = xin[(d + 1) * HW];
                xn0 = fmaf(v0, v0, xn0); xn1 = fmaf(v1, v1, xn1);
                __nv_bfloat16 h0 = __float2bfloat16(v0), h1 = __float2bfloat16(v1);
                *(uint32_t*)(arow + cc * 32 + ww * 4) =
                    (uint32_t)__bfloat16_as_ushort(h0) |
                    ((uint32_t)__bfloat16_as_ushort(h1) << 16);
                *(uint32_t*)(arow + 128 + cc * 32 + ww * 4) =
                    pack_bf16(v0 - __bfloat162float(h0),
                              v1 - __bfloat162float(h1));
            }
        xnorm = xn0 + xn1;
    }
    __syncthreads();

    // ---- load A fragments (resident): warp w owns rows 16w..16w+15 ----
    uint32_t aH[4][4], aL[4][4];
    const int rbase = 16 * w + g;
    {
        const unsigned char* r0 = smem + SM_A + rbase * PITCH + c * 32;
        const unsigned char* r8 = r0 + 8 * PITCH;
        #pragma unroll
        for (int half = 0; half < 2; ++half) {
            const int hb = half * 128;
            uint4 q0a = *(const uint4*)(r0 + hb);
            uint4 q0b = *(const uint4*)(r0 + hb + 16);
            uint4 q8a = *(const uint4*)(r8 + hb);
            uint4 q8b = *(const uint4*)(r8 + hb + 16);
            uint32_t (*A)[4] = half ? aL : aH;
            A[0][0] = q0a.x; A[0][2] = q0a.y;
            A[1][0] = q0a.z; A[1][2] = q0a.w;
            A[2][0] = q0b.x; A[2][2] = q0b.y;
            A[3][0] = q0b.z; A[3][2] = q0b.w;
            A[0][1] = q8a.x; A[0][3] = q8a.y;
            A[1][1] = q8a.z; A[1][3] = q8a.w;
            A[2][1] = q8b.x; A[2][3] = q8b.y;
            A[3][1] = q8b.z; A[3][3] = q8b.w;
        }
    }

    float best[2]  = {3.4e38f, 3.4e38f};
    float best2[2] = {3.4e38f, 3.4e38f};
    int   bidx[2]  = {0, 0};
    int   i2[2]    = {0, 0};

    #pragma unroll 1
    for (int ht = 0; ht < NHT; ++ht) {
        CPA_WAIT1();
        __syncthreads();
        const unsigned char* bbuf = smem + SM_H0 + (ht & 1) * HT_BYTES;

        #pragma unroll 1
        for (int np = 0; np < 4; ++np) {
            // B fragments: 8x LDS.128
            uint32_t bH[2][4][2], bL[2][4][2];
            #pragma unroll
            for (int j = 0; j < 2; ++j) {
                const unsigned char* rb =
                    bbuf + ((2 * np + j) * 8 + g) * PITCH + c * 32;
                uint4 h0 = *(const uint4*)(rb);
                uint4 h1 = *(const uint4*)(rb + 16);
                uint4 l0 = *(const uint4*)(rb + 128);
                uint4 l1 = *(const uint4*)(rb + 144);
                bH[j][0][0] = h0.x; bH[j][0][1] = h0.y;
                bH[j][1][0] = h0.z; bH[j][1][1] = h0.w;
                bH[j][2][0] = h1.x; bH[j][2][1] = h1.y;
                bH[j][3][0] = h1.z; bH[j][3][1] = h1.w;
                bL[j][0][0] = l0.x; bL[j][0][1] = l0.y;
                bL[j][1][0] = l0.z; bL[j][1][1] = l0.w;
                bL[j][2][0] = l1.x; bL[j][2][1] = l1.y;
                bL[j][3][0] = l1.z; bL[j][3][1] = l1.w;
            }
            float D[2][4];
            #pragma unroll
            for (int j = 0; j < 2; ++j)
                #pragma unroll
                for (int q = 0; q < 4; ++q) D[j][q] = 0.f;

            #pragma unroll
            for (int kt = 0; kt < 4; ++kt) {
                MMA(D[0], aH[kt], bH[0][kt]);
                MMA(D[1], aH[kt], bH[1][kt]);
                MMA(D[0], aL[kt], bH[0][kt]);
                MMA(D[1], aL[kt], bH[1][kt]);
                MMA(D[0], aH[kt], bL[0][kt]);
                MMA(D[1], aH[kt], bL[1][kt]);
            }

            // ---- branchless quad-min top-2 epilogue (2 rows) ----
            const int cb0 = ht * HT_CODES + np * 16 + 2 * c;
            const int cb1 = cb0 + 8;
            const float2 cnA = *(const float2*)(smem + SM_CN + cb0 * 4);
            const float2 cnB = *(const float2*)(smem + SM_CN + cb1 * 4);
            #pragma unroll
            for (int rr = 0; rr < 2; ++rr) {
                float s0 = fmaf(-2.f, D[0][2 * rr + 0], cnA.x);
                float s1 = fmaf(-2.f, D[0][2 * rr + 1], cnA.y);
                float s2 = fmaf(-2.f, D[1][2 * rr + 0], cnB.x);
                float s3 = fmaf(-2.f, D[1][2 * rr + 1], cnB.y);
                float m = fminf(fminf(s0, s1), fminf(s2, s3));
                int col = (m == s2) ? cb1 : cb1 + 1;
                col = (m == s1) ? cb0 + 1 : col;
                col = (m == s0) ? cb0 : col;
                UPD(rr, m, col);
            }
        }

        __syncthreads();   // all readers done with buf[ht&1]
        if (ht + 2 < NHT)
            prefetch_ht(sb + SM_H0 + (ht & 1) * HT_BYTES,
                        g_cb + (size_t)(ht + 2) * HT_BYTES, tid);
        CPA_COMMIT();      // empty group when no prefetch -> uniform accounting
    }

    // ---- merge top-2 across the 4 lanes (c) sharing each row ----
    #pragma unroll
    for (int m = 1; m <= 2; m <<= 1) {
        #pragma unroll
        for (int r = 0; r < 2; ++r) {
            float ob  = __shfl_xor_sync(0xffffffffu, best[r], m);
            int   oi  = __shfl_xor_sync(0xffffffffu, bidx[r], m);
            float ob2 = __shfl_xor_sync(0xffffffffu, best2[r], m);
            int   oi2 = __shfl_xor_sync(0xffffffffu, i2[r], m);
            bool ow = (ob < best[r]) || (ob == best[r] && oi < bidx[r]);
            float nb  = ow ? ob : best[r];  int nbi = ow ? oi : bidx[r];
            float c1  = ow ? best[r] : ob;  int c1i = ow ? bidx[r] : oi;
            float c2  = ow ? ob2 : best2[r]; int c2i = ow ? oi2 : i2[r];
            bool s2 = (c2 < c1) || (c2 == c1 && c2i < c1i);
            best[r] = nb; bidx[r] = nbi;
            best2[r] = s2 ? c2 : c1; i2[r] = s2 ? c2i : c1i;
        }
    }
    int* sI1 = (int*)(smem + SM_I1);
    int* sI2 = (int*)(smem + SM_I2);
    if (c == 0) {
        sI1[rbase]     = bidx[0]; sI2[rbase]     = i2[0];
        sI1[rbase + 8] = bidx[1]; sI2[rbase + 8] = i2[1];
    }
    __syncthreads();

    // ---- exact fp32 re-rank of the 2 candidates (position prow) ----
    const int cA = sI1[prow], cB = sI2[prow];
    const float4* pa = (const float4*)(cb + (size_t)cA * DIMS);
    const float4* pb = (const float4*)(cb + (size_t)cB * DIMS);
    float a0 = 0.f, a1 = 0.f, a2 = 0.f, a3 = 0.f;
    float b0 = 0.f, b1 = 0.f, b2 = 0.f, b3 = 0.f;
    #pragma unroll
    for (int d = 0; d < DIMS; d += 4) {
        float x0 = xin[(d + 0) * HW], x1 = xin[(d + 1) * HW];
        float x2 = xin[(d + 2) * HW], x3 = xin[(d + 3) * HW];
        float4 va = pa[d / 4], vb = pb[d / 4];
        a0 = fmaf(x0, va.x, a0); a1 = fmaf(x1, va.y, a1);
        a2 = fmaf(x2, va.z, a2); a3 = fmaf(x3, va.w, a3);
        b0 = fmaf(x0, vb.x, b0); b1 = fmaf(x1, vb.y, b1);
        b2 = fmaf(x2, vb.z, b2); b3 = fmaf(x3, vb.w, b3);
    }
    const float* cnS = (const float*)(smem + SM_CN);
    float sA = fmaf(-2.f, (a0 + a1) + (a2 + a3), cnS[cA]);
    float sB = fmaf(-2.f, (b0 + b1) + (b2 + b3), cnS[cB]);
    int   fin = cA;
    float fs  = sA;
    if (sB < sA || (sB == sA && cB < cA)) { fin = cB; fs = sB; }

    // ---- gather chosen code row, scatter to [B,D,H,W] (tid<64 only) ----
    if (tid < POSC) {
        const float4* cc = (const float4*)(cb + (size_t)fin * DIMS);
        float* o = out + (size_t)b * (DIMS * HW) + hw;
        #pragma unroll
        for (int i = 0; i < DIMS / 4; ++i) {
            float4 v = cc[i];
            o[(4 * i + 0) * HW] = v.x;
            o[(4 * i + 1) * HW] = v.y;
            o[(4 * i + 2) * HW] = v.z;
            o[(4 * i + 3) * HW] = v.w;
        }
    }

    // ---- loss partial (deterministic block tree over 64 positions) ----
    float* red = (float*)(smem + SM_RED);
    red[tid] = (tid < POSC) ? (xnorm + fs) : 0.f;
    __syncthreads();
    #pragma unroll
    for (int s = THREADS / 2; s > 0; s >>= 1) {
        if (tid < s) red[tid] += red[tid + s];
        __syncthreads();
    }
    if (tid == 0) g_partial[blockIdx.x] = red[0];
}

// ---------------------------------------------------------------------------
__global__ void loss_kernel(float* __restrict__ out, int ndhw) {
    __shared__ float red[NBLOCKS];
    red[threadIdx.x] = g_partial[threadIdx.x];
    __syncthreads();
    #pragma unroll
    for (int s = NBLOCKS / 2; s > 0; s >>= 1) {
        if (threadIdx.x < s) red[threadIdx.x] += red[threadIdx.x + s];
        __syncthreads();
    }
    if (threadIdx.x == 0)
        out[ndhw] = 1.25f * red[0] / (float)ndhw;
}

// ---------------------------------------------------------------------------
extern "C" void kernel_launch(void* const* d_in, const int* in_sizes, int n_in,
                              void* d_out, int out_size) {
    const float* latents = (const float*)d_in[0];  // [64,64,32,32]
    const float* cb      = (const float*)d_in[1];  // [1024,64]
    float* out = (float*)d_out;
    const int ndhw = in_sizes[0];                  // 4194304

    static int smem_set = 0;
    if (!smem_set) {
        cudaFuncSetAttribute(vq_mma_kernel,
                             cudaFuncAttributeMaxDynamicSharedMemorySize, SM_TOTAL);
        smem_set = 1;
    }

    prep_kernel<<<64, 128>>>(cb);
    vq_mma_kernel<<<NBLOCKS, THREADS, SM_TOTAL>>>(latents, cb, out);
    loss_kernel<<<1, NBLOCKS>>>(out, ndhw);
}

// round 10
// speedup vs baseline: 1.6699x; 1.0848x over previous
#include <cuda_runtime.h>
#include <cuda_fp16.h>
#include <cstdint>

// VectorQuantizer via mma.sync.m16n8k16 fp16 SINGLE-term (HMMA on sm_103):
// fp16 distance GEMM (3x fewer MMAs than bf16 3-term), per-thread top-3
// argmin window over every score (no quad-min), exact fp32 re-rank of 3.
// latents [64,64,32,32] f32, codebook [1024,64] f32 ->
// out[0..4194303] = codebook[argmin], out[4194304] = 1.25*mean((q-x)^2).

#define DIMS    64
#define KCODES  1024
#define HW      1024
#define THREADS 128
#define NPOS    65536
#define POSC    64
#define NBLOCKS (NPOS / POSC)             // 1024
#define PITCH   144                       // 128B fp16 row + 16B pad (9x16B)
#define TILE_CODES 128
#define TILE_BYTES (TILE_CODES * PITCH)   // 18432
#define NTILES  8

// smem layout
#define SM_A     0                        // 64 x 144 = 9216
#define SM_B0    9216                     // 18432
#define SM_B1    27648                    // 18432
#define SM_CN    46080                    // 1024 f32 (exact)
#define SM_I0    50176                    // 64 int (padded 512)
#define SM_I1    50688
#define SM_I2    51200
#define SM_RED   51712                    // 128 f32
#define SM_TOTAL 52224

__device__ float g_cnorm[KCODES];
__device__ float g_partial[NBLOCKS];
__device__ __align__(16) unsigned char g_cb[KCODES * PITCH];

// Row layout (A and B, per 144B row): lane-group c owns bytes [c*32,c*32+32):
// word w (4B) = fp16 dims (8w+2c, 8w+2c+1). k-step kt uses words 2kt, 2kt+1.

__device__ __forceinline__ uint32_t smem_u32(const void* p) {
    uint32_t a;
    asm("{ .reg .u64 t; cvta.to.shared.u64 t, %1; cvt.u32.u64 %0, t; }"
        : "=r"(a) : "l"(p));
    return a;
}

__device__ __forceinline__ uint32_t pack_h2(float v0, float v1) {
    __half h0 = __float2half_rn(v0), h1 = __float2half_rn(v1);
    return (uint32_t)__half_as_ushort(h0) |
           ((uint32_t)__half_as_ushort(h1) << 16);
}

#define MMA(d, a, bb) \
    asm volatile("mma.sync.aligned.m16n8k16.row.col.f32.f16.f16.f32 " \
                 "{%0,%1,%2,%3}, {%4,%5,%6,%7}, {%8,%9}, {%0,%1,%2,%3};" \
                 : "+f"((d)[0]), "+f"((d)[1]), "+f"((d)[2]), "+f"((d)[3]) \
                 : "r"((a)[0]), "r"((a)[1]), "r"((a)[2]), "r"((a)[3]), \
                   "r"((bb)[0]), "r"((bb)[1]))

__device__ __forceinline__ void cpa16(uint32_t dst, const void* src) {
    asm volatile("cp.async.cg.shared.global [%0], [%1], 16;" :: "r"(dst), "l"(src));
}
#define CPA_COMMIT() asm volatile("cp.async.commit_group;" ::: "memory")
#define CPA_WAIT1()  asm volatile("cp.async.wait_group 1;" ::: "memory")

// branchless sorted top-3 insert; strict < => lowest col wins ties in-stream
#define INS3F(rr, v, ci) \
    do { bool l2 = (v) < bw[rr][2]; bool l1 = (v) < bw[rr][1]; \
         bool l0 = (v) < bw[rr][0]; \
         bw[rr][2] = l1 ? bw[rr][1] : (l2 ? (v) : bw[rr][2]); \
         iw[rr][2] = l1 ? iw[rr][1] : (l2 ? (ci) : iw[rr][2]); \
         bw[rr][1] = l0 ? bw[rr][0] : (l1 ? (v) : bw[rr][1]); \
         iw[rr][1] = l0 ? iw[rr][0] : (l1 ? (ci) : iw[rr][1]); \
         bw[rr][0] = l0 ? (v) : bw[rr][0]; \
         iw[rr][0] = l0 ? (ci) : iw[rr][0]; } while (0)

// tie-aware insert for cross-lane merge (lower index wins on equal score)
#define INS3T(rr, v, ci) \
    do { bool l2 = (v) < bw[rr][2] || ((v) == bw[rr][2] && (ci) < iw[rr][2]); \
         bool l1 = (v) < bw[rr][1] || ((v) == bw[rr][1] && (ci) < iw[rr][1]); \
         bool l0 = (v) < bw[rr][0] || ((v) == bw[rr][0] && (ci) < iw[rr][0]); \
         bw[rr][2] = l1 ? bw[rr][1] : (l2 ? (v) : bw[rr][2]); \
         iw[rr][2] = l1 ? iw[rr][1] : (l2 ? (ci) : iw[rr][2]); \
         bw[rr][1] = l0 ? bw[rr][0] : (l1 ? (v) : bw[rr][1]); \
         iw[rr][1] = l0 ? iw[rr][0] : (l1 ? (ci) : iw[rr][1]); \
         bw[rr][0] = l0 ? (v) : bw[rr][0]; \
         iw[rr][0] = l0 ? (ci) : iw[rr][0]; } while (0)

// ---------------------------------------------------------------------------
// Prep: 8 threads/code -> fp16 row image (c-grouped) + exact fp32 ||c||^2
// ---------------------------------------------------------------------------
__global__ void prep_kernel(const float* __restrict__ cb) {
    const int idx = blockIdx.x * blockDim.x + threadIdx.x;   // 8192 threads
    const int k = idx >> 3;
    const int j = idx & 7;                                   // word index
    const float* row = cb + k * DIMS;
    unsigned char* dst = g_cb + (size_t)k * PITCH;
    float cn = 0.f;
    #pragma unroll
    for (int c = 0; c < 4; ++c) {
        const int d = 8 * j + 2 * c;
        float v0 = row[d], v1 = row[d + 1];
        cn = fmaf(v1, v1, fmaf(v0, v0, cn));
        *(uint32_t*)(dst + c * 32 + j * 4) = pack_h2(v0, v1);
    }
    cn += __shfl_down_sync(0xffffffffu, cn, 4);
    cn += __shfl_down_sync(0xffffffffu, cn, 2);
    cn += __shfl_down_sync(0xffffffffu, cn, 1);
    if (j == 0) g_cnorm[k] = cn;
}

// ---------------------------------------------------------------------------
// Main kernel: 64 positions per CTA, fp16 single-term GEMM
// ---------------------------------------------------------------------------
__global__ __launch_bounds__(THREADS, 4) void vq_mma_kernel(
    const float* __restrict__ latents,
    const float* __restrict__ cb,
    float* __restrict__ out)
{
    extern __shared__ unsigned char smem[];
    const uint32_t sb = smem_u32(smem);
    const int tid  = threadIdx.x;
    const int w    = tid >> 5;
    const int lane = tid & 31;
    const int g    = lane >> 2;
    const int c    = lane & 3;

    // prefetch B tiles 0 and 1 (9 x 16B per thread per tile)
    #pragma unroll
    for (int i = 0; i < 9; ++i)
        cpa16(sb + SM_B0 + tid * 16 + i * 2048, g_cb + tid * 16 + i * 2048);
    CPA_COMMIT();
    #pragma unroll
    for (int i = 0; i < 9; ++i)
        cpa16(sb + SM_B1 + tid * 16 + i * 2048,
              g_cb + TILE_BYTES + tid * 16 + i * 2048);
    CPA_COMMIT();

    // exact cnorm -> smem
    #pragma unroll
    for (int i = tid; i < KCODES / 4; i += THREADS)
        ((float4*)(smem + SM_CN))[i] = ((const float4*)g_cnorm)[i];

    // ---- build A rows (tid < 64: one position each), fp16 c-grouped ----
    const int prow = tid & 63;
    const int p  = blockIdx.x * POSC + prow;
    const int b  = p >> 10;
    const int hw = p & (HW - 1);
    const float* xin = latents + (size_t)b * (DIMS * HW) + hw;
    float xnorm = 0.f;
    if (tid < POSC) {
        unsigned char* arow = smem + SM_A + tid * PITCH;
        float xn0 = 0.f, xn1 = 0.f;
        #pragma unroll
        for (int cc = 0; cc < 4; ++cc)
            #pragma unroll
            for (int ww = 0; ww < 8; ++ww) {
                const int d = 8 * ww + 2 * cc;
                float v0 = xin[d * HW], v1 = xin[(d + 1) * HW];
                xn0 = fmaf(v0, v0, xn0); xn1 = fmaf(v1, v1, xn1);
                *(uint32_t*)(arow + cc * 32 + ww * 4) = pack_h2(v0, v1);
            }
        xnorm = xn0 + xn1;
    }
    __syncthreads();

    // ---- load A fragments (resident): warp w owns rows 16w..16w+15 ----
    uint32_t aa[4][4];                     // [kt][4]
    const int rbase = 16 * w + g;
    {
        const unsigned char* r0 = smem + SM_A + rbase * PITCH + c * 32;
        const unsigned char* r8 = r0 + 8 * PITCH;
        uint4 q0a = *(const uint4*)(r0);
        uint4 q0b = *(const uint4*)(r0 + 16);
        uint4 q8a = *(const uint4*)(r8);
        uint4 q8b = *(const uint4*)(r8 + 16);
        aa[0][0] = q0a.x; aa[0][1] = q8a.x; aa[0][2] = q0a.y; aa[0][3] = q8a.y;
        aa[1][0] = q0a.z; aa[1][1] = q8a.z; aa[1][2] = q0a.w; aa[1][3] = q8a.w;
        aa[2][0] = q0b.x; aa[2][1] = q8b.x; aa[2][2] = q0b.y; aa[2][3] = q8b.y;
        aa[3][0] = q0b.z; aa[3][1] = q8b.z; aa[3][2] = q0b.w; aa[3][3] = q8b.w;
    }

    // per-thread top-3 windows for the 2 rows this thread owns (r, r+8)
    float bw[2][3] = {{3.4e38f, 3.4e38f, 3.4e38f}, {3.4e38f, 3.4e38f, 3.4e38f}};
    int   iw[2][3] = {{0, 0, 0}, {0, 0, 0}};

    #pragma unroll 1
    for (int tb = 0; tb < NTILES; ++tb) {
        CPA_WAIT1();
        __syncthreads();
        const unsigned char* bbuf = smem + SM_B0 + (tb & 1) * TILE_BYTES;

        #pragma unroll 1
        for (int np = 0; np < 8; ++np) {
            // B fragments: 4x LDS.128 (2 n-tiles x 2 uint4)
            uint32_t bb[2][4][2];          // [j][kt][2]
            #pragma unroll
            for (int j = 0; j < 2; ++j) {
                const unsigned char* rb =
                    bbuf + ((2 * np + j) * 8 + g) * PITCH + c * 32;
                uint4 q0 = *(const uint4*)(rb);
                uint4 q1 = *(const uint4*)(rb + 16);
                bb[j][0][0] = q0.x; bb[j][0][1] = q0.y;
                bb[j][1][0] = q0.z; bb[j][1][1] = q0.w;
                bb[j][2][0] = q1.x; bb[j][2][1] = q1.y;
                bb[j][3][0] = q1.z; bb[j][3][1] = q1.w;
            }
            float D[2][4];
            #pragma unroll
            for (int j = 0; j < 2; ++j)
                #pragma unroll
                for (int q = 0; q < 4; ++q) D[j][q] = 0.f;

            #pragma unroll
            for (int kt = 0; kt < 4; ++kt) {
                MMA(D[0], aa[kt], bb[0][kt]);
                MMA(D[1], aa[kt], bb[1][kt]);
            }

            // ---- epilogue: insert ALL 8 scores into per-row top-3 ----
            const int cb0 = tb * TILE_CODES + np * 16 + 2 * c;   // j=0 base
            const int cb1 = cb0 + 8;                             // j=1 base
            const float2 cnA = *(const float2*)(smem + SM_CN + cb0 * 4);
            const float2 cnB = *(const float2*)(smem + SM_CN + cb1 * 4);
            // row rbase (D[.][0..1]):
            {
                float s0 = fmaf(-2.f, D[0][0], cnA.x);
                float s1 = fmaf(-2.f, D[0][1], cnA.y);
                float s2 = fmaf(-2.f, D[1][0], cnB.x);
                float s3 = fmaf(-2.f, D[1][1], cnB.y);
                INS3F(0, s0, cb0); INS3F(0, s1, cb0 + 1);
                INS3F(0, s2, cb1); INS3F(0, s3, cb1 + 1);
            }
            // row rbase+8 (D[.][2..3]):
            {
                float s0 = fmaf(-2.f, D[0][2], cnA.x);
                float s1 = fmaf(-2.f, D[0][3], cnA.y);
                float s2 = fmaf(-2.f, D[1][2], cnB.x);
                float s3 = fmaf(-2.f, D[1][3], cnB.y);
                INS3F(1, s0, cb0); INS3F(1, s1, cb0 + 1);
                INS3F(1, s2, cb1); INS3F(1, s3, cb1 + 1);
            }
        }

        __syncthreads();   // all readers done with buf[tb&1]
        if (tb + 2 < NTILES) {
            const uint32_t bdst = sb + SM_B0 + (tb & 1) * TILE_BYTES;
            #pragma unroll
            for (int i = 0; i < 9; ++i)
                cpa16(bdst + tid * 16 + i * 2048,
                      g_cb + (size_t)(tb + 2) * TILE_BYTES + tid * 16 + i * 2048);
        }
        CPA_COMMIT();      // empty group when no prefetch -> uniform accounting
    }

    // ---- merge top-3 across the 4 lanes (c) sharing each row ----
    #pragma unroll
    for (int m = 1; m <= 2; m <<= 1) {
        float ov[2][3]; int oi[2][3];
        #pragma unroll
        for (int rr = 0; rr < 2; ++rr)
            #pragma unroll
            for (int t = 0; t < 3; ++t) {
                ov[rr][t] = __shfl_xor_sync(0xffffffffu, bw[rr][t], m);
                oi[rr][t] = __shfl_xor_sync(0xffffffffu, iw[rr][t], m);
            }
        #pragma unroll
        for (int rr = 0; rr < 2; ++rr)
            #pragma unroll
            for (int t = 0; t < 3; ++t)
                INS3T(rr, ov[rr][t], oi[rr][t]);
    }
    int* sI0 = (int*)(smem + SM_I0);
    int* sI1 = (int*)(smem + SM_I1);
    int* sI2 = (int*)(smem + SM_I2);
    if (c == 0) {
        sI0[rbase]     = iw[0][0]; sI1[rbase]     = iw[0][1]; sI2[rbase]     = iw[0][2];
        sI0[rbase + 8] = iw[1][0]; sI1[rbase + 8] = iw[1][1]; sI2[rbase + 8] = iw[1][2];
    }
    __syncthreads();

    // ---- exact fp32 re-rank of the 3 candidates (position prow) ----
    const int cA = sI0[prow], cB = sI1[prow], cC = sI2[prow];
    const float4* pa = (const float4*)(cb + (size_t)cA * DIMS);
    const float4* pb = (const float4*)(cb + (size_t)cB * DIMS);
    const float4* pc = (const float4*)(cb + (size_t)cC * DIMS);
    float a0 = 0.f, a1 = 0.f, a2 = 0.f, a3 = 0.f;
    float b0 = 0.f, b1 = 0.f, b2 = 0.f, b3 = 0.f;
    float c0 = 0.f, c1 = 0.f, c2 = 0.f, c3 = 0.f;
    #pragma unroll
    for (int d = 0; d < DIMS; d += 4) {
        float x0 = xin[(d + 0) * HW], x1 = xin[(d + 1) * HW];
        float x2 = xin[(d + 2) * HW], x3 = xin[(d + 3) * HW];
        float4 va = pa[d / 4], vb = pb[d / 4], vc = pc[d / 4];
        a0 = fmaf(x0, va.x, a0); a1 = fmaf(x1, va.y, a1);
        a2 = fmaf(x2, va.z, a2); a3 = fmaf(x3, va.w, a3);
        b0 = fmaf(x0, vb.x, b0); b1 = fmaf(x1, vb.y, b1);
        b2 = fmaf(x2, vb.z, b2); b3 = fmaf(x3, vb.w, b3);
        c0 = fmaf(x0, vc.x, c0); c1 = fmaf(x1, vc.y, c1);
        c2 = fmaf(x2, vc.z, c2); c3 = fmaf(x3, vc.w, c3);
    }
    const float* cnS = (const float*)(smem + SM_CN);
    float sA = fmaf(-2.f, (a0 + a1) + (a2 + a3), cnS[cA]);
    float sB = fmaf(-2.f, (b0 + b1) + (b2 + b3), cnS[cB]);
    float sC = fmaf(-2.f, (c0 + c1) + (c2 + c3), cnS[cC]);
    int   fin = cA;
    float fs  = sA;
    if (sB < fs || (sB == fs && cB < fin)) { fin = cB; fs = sB; }
    if (sC < fs || (sC == fs && cC < fin)) { fin = cC; fs = sC; }

    // ---- gather chosen code row, scatter to [B,D,H,W] (tid<64 only) ----
    if (tid < POSC) {
        const float4* cc = (const float4*)(cb + (size_t)fin * DIMS);
        float* o = out + (size_t)b * (DIMS * HW) + hw;
        #pragma unroll
        for (int i = 0; i < DIMS / 4; ++i) {
            float4 v = cc[i];
            o[(4 * i + 0) * HW] = v.x;
            o[(4 * i + 1) * HW] = v.y;
            o[(4 * i + 2) * HW] = v.z;
            o[(4 * i + 3) * HW] = v.w;
        }
    }

    // ---- loss partial (deterministic block tree over 64 positions) ----
    float* red = (float*)(smem + SM_RED);
    red[tid] = (tid < POSC) ? (xnorm + fs) : 0.f;
    __syncthreads();
    #pragma unroll
    for (int s = THREADS / 2; s > 0; s >>= 1) {
        if (tid < s) red[tid] += red[tid + s];
        __syncthreads();
    }
    if (tid == 0) g_partial[blockIdx.x] = red[0];
}

// ---------------------------------------------------------------------------
__global__ void loss_kernel(float* __restrict__ out, int ndhw) {
    __shared__ float red[NBLOCKS];
    red[threadIdx.x] = g_partial[threadIdx.x];
    __syncthreads();
    #pragma unroll
    for (int s = NBLOCKS / 2; s > 0; s >>= 1) {
        if (threadIdx.x < s) red[threadIdx.x] += red[threadIdx.x + s];
        __syncthreads();
    }
    if (threadIdx.x == 0)
        out[ndhw] = 1.25f * red[0] / (float)ndhw;
}

// ---------------------------------------------------------------------------
extern "C" void kernel_launch(void* const* d_in, const int* in_sizes, int n_in,
                              void* d_out, int out_size) {
    const float* latents = (const float*)d_in[0];  // [64,64,32,32]
    const float* cb      = (const float*)d_in[1];  // [1024,64]
    float* out = (float*)d_out;
    const int ndhw = in_sizes[0];                  // 4194304

    static int smem_set = 0;
    if (!smem_set) {
        cudaFuncSetAttribute(vq_mma_kernel,
                             cudaFuncAttributeMaxDynamicSharedMemorySize, SM_TOTAL);
        smem_set = 1;
    }

    prep_kernel<<<64, 128>>>(cb);
    vq_mma_kernel<<<NBLOCKS, THREADS, SM_TOTAL>>>(latents, cb, out);
    loss_kernel<<<1, NBLOCKS>>>(out, ndhw);
}